// round 14
// baseline (speedup 1.0000x reference)
#include <cuda_runtime.h>
#include <stdint.h>

#define NMAX 50000
#define EMAX 800000
#define DIM 128
#define NCHUNK 4

// ---------------- scratch (static device globals; no allocation) ----------------
__device__ float g_buf0[(size_t)NMAX * DIM];   // layer-1 GEMM output H1
__device__ float g_buf1[(size_t)NMAX * DIM];   // agg1 output / gemm2 input
__device__ float g_buf2[(size_t)NMAX * DIM];   // layer-2 GEMM output H2
__device__ float g_h3[NMAX * 2];
__device__ float g_dis[NMAX];
__device__ int   g_cnt[NMAX];
__device__ int   g_starts[NMAX];
__device__ int   g_cursor[NMAX];
__device__ long long g_csr[EMAX];              // packed: low32 = src, high32 = w bits
__device__ int   g_total;

// ---------------- packed f32x2 helpers (Blackwell FFMA2 — PTX-only) ----------------
__device__ __forceinline__ unsigned long long packf2(float lo, float hi) {
    unsigned long long r;
    asm("mov.b64 %0, {%1, %2};" : "=l"(r) : "f"(lo), "f"(hi));
    return r;
}
__device__ __forceinline__ void fmaf2(unsigned long long& d,
                                      unsigned long long a, unsigned long long b) {
    asm("fma.rn.f32x2 %0, %1, %2, %0;" : "+l"(d) : "l"(a), "l"(b));
}
__device__ __forceinline__ float2 unpackf2(unsigned long long v) {
    float lo, hi;
    asm("mov.b64 {%0, %1}, %2;" : "=f"(lo), "=f"(hi) : "l"(v));
    return make_float2(lo, hi);
}

// ---------------- JAX Threefry-2x32 (20 rounds) ----------------
__host__ __device__ __forceinline__ void tf2x32(uint32_t k0, uint32_t k1,
                                                uint32_t x0, uint32_t x1,
                                                uint32_t& o0, uint32_t& o1) {
    uint32_t ks2 = k0 ^ k1 ^ 0x1BD11BDAu;
    x0 += k0; x1 += k1;
#define TFROT(a, b, r) { a += b; b = ((b << (r)) | (b >> (32 - (r)))); b ^= a; }
    TFROT(x0, x1, 13) TFROT(x0, x1, 15) TFROT(x0, x1, 26) TFROT(x0, x1, 6)
    x0 += k1;  x1 += ks2 + 1u;
    TFROT(x0, x1, 17) TFROT(x0, x1, 29) TFROT(x0, x1, 16) TFROT(x0, x1, 24)
    x0 += ks2; x1 += k0 + 2u;
    TFROT(x0, x1, 13) TFROT(x0, x1, 15) TFROT(x0, x1, 26) TFROT(x0, x1, 6)
    x0 += k0;  x1 += k1 + 3u;
    TFROT(x0, x1, 17) TFROT(x0, x1, 29) TFROT(x0, x1, 16) TFROT(x0, x1, 24)
    x0 += k1;  x1 += ks2 + 4u;
    TFROT(x0, x1, 13) TFROT(x0, x1, 15) TFROT(x0, x1, 26) TFROT(x0, x1, 6)
    x0 += ks2; x1 += k0 + 5u;
#undef TFROT
    o0 = x0; o1 = x1;
}

__device__ __forceinline__ bool drop_keep(uint32_t ka, uint32_t kb, uint32_t i) {
    uint32_t y0, y1;
    tf2x32(ka, kb, 0u, i, y0, y1);
    uint32_t bits = y0 ^ y1;
    float u = __uint_as_float((bits >> 9) | 0x3f800000u) - 1.0f;
    return u < 0.5f;
}

// ---------------- graph prep ----------------
__global__ void k_zero_cnt(int n) {
    int i = blockIdx.x * blockDim.x + threadIdx.x;
    if (i == 0) g_total = 0;
    if (i < n) g_cnt[i] = 0;
}

__global__ void k_count(const int* __restrict__ ei, int E) {
    int q = blockIdx.x * blockDim.x + threadIdx.x;
    int E4 = E >> 2;
    if (q < E4) {
        int4 d = ((const int4*)(ei + E))[q];
        atomicAdd(&g_cnt[d.x], 1);
        atomicAdd(&g_cnt[d.y], 1);
        atomicAdd(&g_cnt[d.z], 1);
        atomicAdd(&g_cnt[d.w], 1);
    } else {
        int r = (E4 << 2) + (q - E4);
        if (r < E) atomicAdd(&g_cnt[ei[E + r]], 1);
    }
}

// dis + region reservation with warp-aggregated atomic (non-padded)
__global__ void k_disres(int n) {
    int i = blockIdx.x * blockDim.x + threadIdx.x;
    int lane = threadIdx.x & 31;
    int c = (i < n) ? g_cnt[i] : 0;
    if (i < n) g_dis[i] = rsqrtf((float)(c + 1));
    int pfx = c;
#pragma unroll
    for (int off = 1; off < 32; off <<= 1) {
        int t = __shfl_up_sync(0xffffffffu, pfx, off);
        if (lane >= off) pfx += t;
    }
    int tot = __shfl_sync(0xffffffffu, pfx, 31);
    int base = 0;
    if (lane == 31) base = atomicAdd(&g_total, tot);
    base = __shfl_sync(0xffffffffu, base, 31);
    int st = base + pfx - c;
    if (i < n) { g_starts[i] = st; g_cursor[i] = st; }
}

// scatter: 4 edges per thread (MLP), packed 8-byte CSR entries
__global__ void k_scatter(const int* __restrict__ ei, int E) {
    int q = blockIdx.x * blockDim.x + threadIdx.x;
    int E4 = E >> 2;
    if (q < E4) {
        int4 s4 = ((const int4*)ei)[q];
        int4 d4 = ((const int4*)(ei + E))[q];
        float ds0 = g_dis[s4.x], ds1 = g_dis[s4.y], ds2 = g_dis[s4.z], ds3 = g_dis[s4.w];
        float dd0 = g_dis[d4.x], dd1 = g_dis[d4.y], dd2 = g_dis[d4.z], dd3 = g_dis[d4.w];
        int p0 = atomicAdd(&g_cursor[d4.x], 1);
        int p1 = atomicAdd(&g_cursor[d4.y], 1);
        int p2 = atomicAdd(&g_cursor[d4.z], 1);
        int p3 = atomicAdd(&g_cursor[d4.w], 1);
        g_csr[p0] = ((long long)(unsigned)__float_as_int(ds0 * dd0) << 32) | (unsigned)s4.x;
        g_csr[p1] = ((long long)(unsigned)__float_as_int(ds1 * dd1) << 32) | (unsigned)s4.y;
        g_csr[p2] = ((long long)(unsigned)__float_as_int(ds2 * dd2) << 32) | (unsigned)s4.z;
        g_csr[p3] = ((long long)(unsigned)__float_as_int(ds3 * dd3) << 32) | (unsigned)s4.w;
    } else {
        int r = (E4 << 2) + (q - E4);
        if (r < E) {
            int s = ei[r];
            int d = ei[E + r];
            float w = g_dis[s] * g_dis[d];
            int p = atomicAdd(&g_cursor[d], 1);
            g_csr[p] = ((long long)(unsigned)__float_as_int(w) << 32) | (unsigned)s;
        }
    }
}

// ---------------- GEMM: OUT[r,128] = X[r,128] @ W[128,128] for r in [row_base,row_end) --
// 128x128 tile, 256 threads, row-pair f32x2 FFMA2.
#define XS_STRIDE 136

__global__ void __launch_bounds__(256, 2)
k_gemm128(const float* __restrict__ Xext, const float* __restrict__ W,
          int osel, int row_base, int row_end) {
    __shared__ float Ws[16 * 128];
    __shared__ float Xs[16 * XS_STRIDE];

    const float* X = Xext ? Xext : g_buf1;
    float* H = osel ? g_buf2 : g_buf0;

    int t = threadIdx.x;
    int row0 = row_base + blockIdx.x * 128;
    int tx = t & 15;
    int ty = t >> 4;

    unsigned long long accp[4][8];
#pragma unroll
    for (int p = 0; p < 4; p++)
#pragma unroll
        for (int j = 0; j < 8; j++) accp[p][j] = 0ull;

    for (int c = 0; c < 8; c++) {
        const float4* Wg = (const float4*)(W + c * 16 * 128);
        float4* Wsv = (float4*)Ws;
        Wsv[t] = Wg[t];
        Wsv[t + 256] = Wg[t + 256];

#pragma unroll
        for (int i = 0; i < 2; i++) {
            int q = t + i * 256;
            int r = q >> 2;
            int kk = (q & 3) * 4;
            float4 v = make_float4(0.f, 0.f, 0.f, 0.f);
            if (row0 + r < row_end)
                v = *(const float4*)(X + (size_t)(row0 + r) * DIM + c * 16 + kk);
            Xs[(kk + 0) * XS_STRIDE + r] = v.x;
            Xs[(kk + 1) * XS_STRIDE + r] = v.y;
            Xs[(kk + 2) * XS_STRIDE + r] = v.z;
            Xs[(kk + 3) * XS_STRIDE + r] = v.w;
        }
        __syncthreads();

#pragma unroll
        for (int k = 0; k < 16; k++) {
            ulonglong2 xA = *(const ulonglong2*)&Xs[k * XS_STRIDE + ty * 8];
            ulonglong2 xB = *(const ulonglong2*)&Xs[k * XS_STRIDE + ty * 8 + 4];
            unsigned long long xp[4] = {xA.x, xA.y, xB.x, xB.y};
            float4 wa = *(const float4*)&Ws[k * 128 + tx * 8];
            float4 wb = *(const float4*)&Ws[k * 128 + tx * 8 + 4];
            unsigned long long wd[8];
            wd[0] = packf2(wa.x, wa.x);
            wd[1] = packf2(wa.y, wa.y);
            wd[2] = packf2(wa.z, wa.z);
            wd[3] = packf2(wa.w, wa.w);
            wd[4] = packf2(wb.x, wb.x);
            wd[5] = packf2(wb.y, wb.y);
            wd[6] = packf2(wb.z, wb.z);
            wd[7] = packf2(wb.w, wb.w);
#pragma unroll
            for (int p = 0; p < 4; p++)
#pragma unroll
                for (int j = 0; j < 8; j++) fmaf2(accp[p][j], xp[p], wd[j]);
        }
        __syncthreads();
    }

#pragma unroll
    for (int p = 0; p < 4; p++) {
        float lo[8], hi[8];
#pragma unroll
        for (int j = 0; j < 8; j++) {
            float2 u = unpackf2(accp[p][j]);
            lo[j] = u.x; hi[j] = u.y;
        }
        int r0 = row0 + ty * 8 + 2 * p;
        if (r0 < row_end) {
            *(float4*)(H + (size_t)r0 * DIM + tx * 8) = make_float4(lo[0], lo[1], lo[2], lo[3]);
            *(float4*)(H + (size_t)r0 * DIM + tx * 8 + 4) = make_float4(lo[4], lo[5], lo[6], lo[7]);
        }
        if (r0 + 1 < row_end) {
            *(float4*)(H + (size_t)(r0 + 1) * DIM + tx * 8) = make_float4(hi[0], hi[1], hi[2], hi[3]);
            *(float4*)(H + (size_t)(r0 + 1) * DIM + tx * 8 + 4) = make_float4(hi[4], hi[5], hi[6], hi[7]);
        }
    }
}

// ------- aggregation + bias + leaky_relu + dropout (+ optional fused x@W3) -------
// H selected by hsel (0: g_buf0, 1: g_buf2). Nodes [v_base, v_end).
__global__ void k_agg128(const float* __restrict__ bias, const float* __restrict__ W3,
                         int hsel, int v_base, int v_end,
                         uint32_t ka, uint32_t kb) {
    const float* H = hsel ? g_buf2 : g_buf0;
    int g = blockIdx.x * blockDim.x + threadIdx.x;
    int v = v_base + (g >> 5);
    if (v >= v_end) return;
    int lane = g & 31;
    int s0 = g_starts[v];
    int cnt = g_cnt[v];

    float4 acc = make_float4(0.f, 0.f, 0.f, 0.f);
    for (int base = 0; base < cnt; base += 32) {
        int si = 0; float wi = 0.f;
        if (base + lane < cnt) {
            long long p = g_csr[s0 + base + lane];
            si = (int)(unsigned)(p & 0xffffffffll);
            wi = __int_as_float((int)(p >> 32));
        }
        int m = min(32, cnt - base);
        for (int j = 0; j < m; j++) {
            int s = __shfl_sync(0xffffffffu, si, j);
            float w = __shfl_sync(0xffffffffu, wi, j);
            float4 hv = *(const float4*)(H + (size_t)s * DIM + lane * 4);
            acc.x += w * hv.x; acc.y += w * hv.y;
            acc.z += w * hv.z; acc.w += w * hv.w;
        }
    }
    float dv = g_dis[v];
    float ws = dv * dv;
    float4 hv = *(const float4*)(H + (size_t)v * DIM + lane * 4);
    float4 bv = *(const float4*)(bias + lane * 4);
    acc.x += ws * hv.x + bv.x;
    acc.y += ws * hv.y + bv.y;
    acc.z += ws * hv.z + bv.z;
    acc.w += ws * hv.w + bv.w;

    // leaky_relu + exact-JAX dropout
    {
        uint32_t i0 = (uint32_t)v * DIM + lane * 4;
        float a[4] = {acc.x, acc.y, acc.z, acc.w};
#pragma unroll
        for (int c2 = 0; c2 < 4; c2++) {
            float vv = a[c2];
            vv = (vv >= 0.f) ? vv : 0.01f * vv;
            a[c2] = drop_keep(ka, kb, i0 + c2) ? (vv + vv) : 0.f;
        }
        acc.x = a[0]; acc.y = a[1]; acc.z = a[2]; acc.w = a[3];
    }

    if (W3 == nullptr) {
        *(float4*)(g_buf1 + (size_t)v * DIM + lane * 4) = acc;
    } else {
        float4 wA = *(const float4*)(W3 + lane * 8);
        float4 wB = *(const float4*)(W3 + lane * 8 + 4);
        float a0 = acc.x * wA.x + acc.y * wA.z + acc.z * wB.x + acc.w * wB.z;
        float a1 = acc.x * wA.y + acc.y * wA.w + acc.z * wB.y + acc.w * wB.w;
#pragma unroll
        for (int off = 16; off > 0; off >>= 1) {
            a0 += __shfl_xor_sync(0xffffffffu, a0, off);
            a1 += __shfl_xor_sync(0xffffffffu, a1, off);
        }
        if (lane == 0) { g_h3[v * 2] = a0; g_h3[v * 2 + 1] = a1; }
    }
}

// ---------------- final aggregation + bias + log_softmax (4 lanes/node) ----------------
__global__ void k_final(const float* __restrict__ b3, float* __restrict__ out, int n) {
    int g = blockIdx.x * blockDim.x + threadIdx.x;
    int v = g >> 2;
    if (v >= n) return;
    int sub = g & 3;
    int s0 = g_starts[v];
    int cnt = g_cnt[v];
    float a0 = 0.f, a1 = 0.f;
    for (int i = sub; i < cnt; i += 4) {
        long long p = g_csr[s0 + i];
        int s = (int)(unsigned)(p & 0xffffffffll);
        float w = __int_as_float((int)(p >> 32));
        a0 += w * g_h3[s * 2];
        a1 += w * g_h3[s * 2 + 1];
    }
#pragma unroll
    for (int off = 1; off < 4; off <<= 1) {
        a0 += __shfl_xor_sync(0xffffffffu, a0, off);
        a1 += __shfl_xor_sync(0xffffffffu, a1, off);
    }
    if (sub == 0) {
        float dv = g_dis[v];
        float wsv = dv * dv;
        a0 += wsv * g_h3[v * 2]     + b3[0];
        a1 += wsv * g_h3[v * 2 + 1] + b3[1];
        float m = fmaxf(a0, a1);
        float lse = m + logf(expf(a0 - m) + expf(a1 - m));
        out[v * 2]     = a0 - lse;
        out[v * 2 + 1] = a1 - lse;
    }
}

// ---------------- launch (fork-join + layer1/2 chunk pipeline; capture safe) ----------------
extern "C" void kernel_launch(void* const* d_in, const int* in_sizes, int n_in,
                              void* d_out, int out_size) {
    const float* x  = (const float*)d_in[0];
    const int*   ei = (const int*)d_in[1];
    const float* W1 = (const float*)d_in[2];
    const float* b1 = (const float*)d_in[3];
    const float* W2 = (const float*)d_in[4];
    const float* b2 = (const float*)d_in[5];
    const float* W3 = (const float*)d_in[6];
    const float* b3 = (const float*)d_in[7];
    float* out = (float*)d_out;

    int n = in_sizes[0] / DIM;      // 50000
    int E = in_sizes[1] / 2;        // 800000

    uint32_t k1a, k1b, k2a, k2b;
    tf2x32(0u, 42u, 0u, 0u, k1a, k1b);
    tf2x32(0u, 42u, 0u, 1u, k2a, k2b);

    static cudaStream_t s_side = nullptr;
    static cudaEvent_t ev_fork = nullptr, ev_join = nullptr;
    static cudaEvent_t ev_a[NCHUNK], ev_g[NCHUNK];
    if (s_side == nullptr) {
        cudaStreamCreateWithFlags(&s_side, cudaStreamNonBlocking);
        cudaEventCreateWithFlags(&ev_fork, cudaEventDisableTiming);
        cudaEventCreateWithFlags(&ev_join, cudaEventDisableTiming);
        for (int c = 0; c < NCHUNK; c++) {
            cudaEventCreateWithFlags(&ev_a[c], cudaEventDisableTiming);
            cudaEventCreateWithFlags(&ev_g[c], cudaEventDisableTiming);
        }
    }

    int nb_n = (n + 255) / 256;
    int nb_f = (n * 4 + 255) / 256;
    int nb_w_full = (n * 32 + 255) / 256;
    int nb_g_full = (n + 127) / 128;
    int E4 = E >> 2;
    int nb_q = (E4 + (E & 3) + 255) / 256;
    int cs = (n + NCHUNK - 1) / NCHUNK;

    // fork: CSR prep on side stream, concurrent with GEMM1 on main stream
    cudaEventRecord(ev_fork, 0);
    cudaStreamWaitEvent(s_side, ev_fork, 0);
    k_zero_cnt<<<nb_n, 256, 0, s_side>>>(n);
    k_count<<<nb_q, 256, 0, s_side>>>(ei, E);
    k_disres<<<nb_n, 256, 0, s_side>>>(n);
    k_scatter<<<nb_q, 256, 0, s_side>>>(ei, E);
    cudaEventRecord(ev_join, s_side);

    k_gemm128<<<nb_g_full, 256>>>(x, W1, 0, 0, n);   // gemm1 -> g_buf0

    cudaStreamWaitEvent(0, ev_join, 0);              // join before agg1

    // pipelined: agg1 chunk c (main) -> gemm2 chunk c (side, writes g_buf2)
    for (int c = 0; c < NCHUNK; c++) {
        int v0 = c * cs;
        int v1 = (v0 + cs < n) ? v0 + cs : n;
        int nb_w = ((v1 - v0) * 32 + 255) / 256;
        k_agg128<<<nb_w, 256>>>(b1, nullptr, 0, v0, v1, k1a, k1b);
        cudaEventRecord(ev_a[c], 0);
        cudaStreamWaitEvent(s_side, ev_a[c], 0);
        int nb_g = ((v1 - v0) + 127) / 128;
        k_gemm128<<<nb_g, 256, 0, s_side>>>(nullptr, W2, 1, v0, v1);
        cudaEventRecord(ev_g[c], s_side);
    }
    cudaStreamWaitEvent(0, ev_g[NCHUNK - 1], 0);     // side stream is serial

    // layer 2 agg (+ fused layer-3 GEMM), reads g_buf2
    k_agg128<<<nb_w_full, 256>>>(b2, W3, 1, 0, n, k2a, k2b);
    // final aggregation + log_softmax
    k_final<<<nb_f, 256>>>(b3, out, n);
}

// round 17
// speedup vs baseline: 1.1436x; 1.1436x over previous
#include <cuda_runtime.h>
#include <stdint.h>

#define NMAX 50000
#define EMAX 800000
#define DIM 128

// ---------------- scratch (static device globals; no allocation) ----------------
__device__ float g_buf0[(size_t)NMAX * DIM];   // GEMM output H
__device__ float g_buf1[(size_t)NMAX * DIM];   // agg1 output / gemm2 input
__device__ float g_h3[NMAX * 2];
__device__ float g_dis[NMAX];
__device__ int   g_cnt[NMAX];
__device__ int   g_starts[NMAX];
__device__ int   g_cursor[NMAX];
__device__ long long g_csr[EMAX];              // packed: low32 = src, high32 = w bits
__device__ int   g_total;

// ---------------- packed f32x2 helpers (Blackwell FFMA2 — PTX-only) ----------------
__device__ __forceinline__ unsigned long long packf2(float lo, float hi) {
    unsigned long long r;
    asm("mov.b64 %0, {%1, %2};" : "=l"(r) : "f"(lo), "f"(hi));
    return r;
}
__device__ __forceinline__ void fmaf2(unsigned long long& d,
                                      unsigned long long a, unsigned long long b) {
    asm("fma.rn.f32x2 %0, %1, %2, %0;" : "+l"(d) : "l"(a), "l"(b));
}
__device__ __forceinline__ float2 unpackf2(unsigned long long v) {
    float lo, hi;
    asm("mov.b64 {%0, %1}, %2;" : "=f"(lo), "=f"(hi) : "l"(v));
    return make_float2(lo, hi);
}

// ---------------- JAX Threefry-2x32 (20 rounds) ----------------
__host__ __device__ __forceinline__ void tf2x32(uint32_t k0, uint32_t k1,
                                                uint32_t x0, uint32_t x1,
                                                uint32_t& o0, uint32_t& o1) {
    uint32_t ks2 = k0 ^ k1 ^ 0x1BD11BDAu;
    x0 += k0; x1 += k1;
#define TFROT(a, b, r) { a += b; b = ((b << (r)) | (b >> (32 - (r)))); b ^= a; }
    TFROT(x0, x1, 13) TFROT(x0, x1, 15) TFROT(x0, x1, 26) TFROT(x0, x1, 6)
    x0 += k1;  x1 += ks2 + 1u;
    TFROT(x0, x1, 17) TFROT(x0, x1, 29) TFROT(x0, x1, 16) TFROT(x0, x1, 24)
    x0 += ks2; x1 += k0 + 2u;
    TFROT(x0, x1, 13) TFROT(x0, x1, 15) TFROT(x0, x1, 26) TFROT(x0, x1, 6)
    x0 += k0;  x1 += k1 + 3u;
    TFROT(x0, x1, 17) TFROT(x0, x1, 29) TFROT(x0, x1, 16) TFROT(x0, x1, 24)
    x0 += k1;  x1 += ks2 + 4u;
    TFROT(x0, x1, 13) TFROT(x0, x1, 15) TFROT(x0, x1, 26) TFROT(x0, x1, 6)
    x0 += ks2; x1 += k0 + 5u;
#undef TFROT
    o0 = x0; o1 = x1;
}

__device__ __forceinline__ bool drop_keep(uint32_t ka, uint32_t kb, uint32_t i) {
    uint32_t y0, y1;
    tf2x32(ka, kb, 0u, i, y0, y1);
    uint32_t bits = y0 ^ y1;
    float u = __uint_as_float((bits >> 9) | 0x3f800000u) - 1.0f;
    return u < 0.5f;
}

// ---------------- graph prep ----------------
__global__ void k_zero_cnt(int n) {
    int i = blockIdx.x * blockDim.x + threadIdx.x;
    if (i == 0) g_total = 0;
    if (i < n) g_cnt[i] = 0;
}

__global__ void k_count(const int* __restrict__ ei, int E) {
    int q = blockIdx.x * blockDim.x + threadIdx.x;
    int E4 = E >> 2;
    if (q < E4) {
        int4 d = ((const int4*)(ei + E))[q];
        atomicAdd(&g_cnt[d.x], 1);
        atomicAdd(&g_cnt[d.y], 1);
        atomicAdd(&g_cnt[d.z], 1);
        atomicAdd(&g_cnt[d.w], 1);
    } else {
        int r = (E4 << 2) + (q - E4);
        if (r < E) atomicAdd(&g_cnt[ei[E + r]], 1);
    }
}

// dis + region reservation with warp-aggregated atomic
__global__ void k_disres(int n) {
    int i = blockIdx.x * blockDim.x + threadIdx.x;
    int lane = threadIdx.x & 31;
    int c = (i < n) ? g_cnt[i] : 0;
    if (i < n) g_dis[i] = rsqrtf((float)(c + 1));
    int pfx = c;
#pragma unroll
    for (int off = 1; off < 32; off <<= 1) {
        int t = __shfl_up_sync(0xffffffffu, pfx, off);
        if (lane >= off) pfx += t;
    }
    int tot = __shfl_sync(0xffffffffu, pfx, 31);
    int base = 0;
    if (lane == 31) base = atomicAdd(&g_total, tot);
    base = __shfl_sync(0xffffffffu, base, 31);
    int st = base + pfx - c;
    if (i < n) { g_starts[i] = st; g_cursor[i] = st; }
}

// scatter: 4 edges per thread (MLP), packed 8-byte CSR entries
__global__ void k_scatter(const int* __restrict__ ei, int E) {
    int q = blockIdx.x * blockDim.x + threadIdx.x;
    int E4 = E >> 2;
    if (q < E4) {
        int4 s4 = ((const int4*)ei)[q];
        int4 d4 = ((const int4*)(ei + E))[q];
        float ds0 = g_dis[s4.x], ds1 = g_dis[s4.y], ds2 = g_dis[s4.z], ds3 = g_dis[s4.w];
        float dd0 = g_dis[d4.x], dd1 = g_dis[d4.y], dd2 = g_dis[d4.z], dd3 = g_dis[d4.w];
        int p0 = atomicAdd(&g_cursor[d4.x], 1);
        int p1 = atomicAdd(&g_cursor[d4.y], 1);
        int p2 = atomicAdd(&g_cursor[d4.z], 1);
        int p3 = atomicAdd(&g_cursor[d4.w], 1);
        g_csr[p0] = ((long long)(unsigned)__float_as_int(ds0 * dd0) << 32) | (unsigned)s4.x;
        g_csr[p1] = ((long long)(unsigned)__float_as_int(ds1 * dd1) << 32) | (unsigned)s4.y;
        g_csr[p2] = ((long long)(unsigned)__float_as_int(ds2 * dd2) << 32) | (unsigned)s4.z;
        g_csr[p3] = ((long long)(unsigned)__float_as_int(ds3 * dd3) << 32) | (unsigned)s4.w;
    } else {
        int r = (E4 << 2) + (q - E4);
        if (r < E) {
            int s = ei[r];
            int d = ei[E + r];
            float w = g_dis[s] * g_dis[d];
            int p = atomicAdd(&g_cursor[d], 1);
            g_csr[p] = ((long long)(unsigned)__float_as_int(w) << 32) | (unsigned)s;
        }
    }
}

// ---------------- GEMM: g_buf0[nrows,128] = X[nrows,128] @ W[128,128] ----------------
// 128x128 tile, 256 threads, row-pair f32x2 FFMA2; x pairs loaded as 64-bit.
#define XS_STRIDE 136

__global__ void __launch_bounds__(256, 2)
k_gemm128(const float* __restrict__ Xext, const float* __restrict__ W, int nrows) {
    __shared__ float Ws[16 * 128];
    __shared__ float Xs[16 * XS_STRIDE];

    const float* X = Xext ? Xext : g_buf1;
    float* H = g_buf0;

    int t = threadIdx.x;
    int row0 = blockIdx.x * 128;
    int tx = t & 15;
    int ty = t >> 4;

    unsigned long long accp[4][8];
#pragma unroll
    for (int p = 0; p < 4; p++)
#pragma unroll
        for (int j = 0; j < 8; j++) accp[p][j] = 0ull;

    for (int c = 0; c < 8; c++) {
        const float4* Wg = (const float4*)(W + c * 16 * 128);
        float4* Wsv = (float4*)Ws;
        Wsv[t] = Wg[t];
        Wsv[t + 256] = Wg[t + 256];

#pragma unroll
        for (int i = 0; i < 2; i++) {
            int q = t + i * 256;
            int r = q >> 2;
            int kk = (q & 3) * 4;
            float4 v = make_float4(0.f, 0.f, 0.f, 0.f);
            if (row0 + r < nrows)
                v = *(const float4*)(X + (size_t)(row0 + r) * DIM + c * 16 + kk);
            Xs[(kk + 0) * XS_STRIDE + r] = v.x;
            Xs[(kk + 1) * XS_STRIDE + r] = v.y;
            Xs[(kk + 2) * XS_STRIDE + r] = v.z;
            Xs[(kk + 3) * XS_STRIDE + r] = v.w;
        }
        __syncthreads();

#pragma unroll
        for (int k = 0; k < 16; k++) {
            ulonglong2 xA = *(const ulonglong2*)&Xs[k * XS_STRIDE + ty * 8];
            ulonglong2 xB = *(const ulonglong2*)&Xs[k * XS_STRIDE + ty * 8 + 4];
            unsigned long long xp[4] = {xA.x, xA.y, xB.x, xB.y};
            float4 wa = *(const float4*)&Ws[k * 128 + tx * 8];
            float4 wb = *(const float4*)&Ws[k * 128 + tx * 8 + 4];
            unsigned long long wd[8];
            wd[0] = packf2(wa.x, wa.x);
            wd[1] = packf2(wa.y, wa.y);
            wd[2] = packf2(wa.z, wa.z);
            wd[3] = packf2(wa.w, wa.w);
            wd[4] = packf2(wb.x, wb.x);
            wd[5] = packf2(wb.y, wb.y);
            wd[6] = packf2(wb.z, wb.z);
            wd[7] = packf2(wb.w, wb.w);
#pragma unroll
            for (int p = 0; p < 4; p++)
#pragma unroll
                for (int j = 0; j < 8; j++) fmaf2(accp[p][j], xp[p], wd[j]);
        }
        __syncthreads();
    }

#pragma unroll
    for (int p = 0; p < 4; p++) {
        float lo[8], hi[8];
#pragma unroll
        for (int j = 0; j < 8; j++) {
            float2 u = unpackf2(accp[p][j]);
            lo[j] = u.x; hi[j] = u.y;
        }
        int r0 = row0 + ty * 8 + 2 * p;
        if (r0 < nrows) {
            *(float4*)(H + (size_t)r0 * DIM + tx * 8) = make_float4(lo[0], lo[1], lo[2], lo[3]);
            *(float4*)(H + (size_t)r0 * DIM + tx * 8 + 4) = make_float4(lo[4], lo[5], lo[6], lo[7]);
        }
        if (r0 + 1 < nrows) {
            *(float4*)(H + (size_t)(r0 + 1) * DIM + tx * 8) = make_float4(hi[0], hi[1], hi[2], hi[3]);
            *(float4*)(H + (size_t)(r0 + 1) * DIM + tx * 8 + 4) = make_float4(hi[4], hi[5], hi[6], hi[7]);
        }
    }
}

// ------- aggregation + bias + leaky_relu + dropout (+ optional fused x@W3) -------
// Inner gather unrolled by 4 with independent accumulators: 4 outstanding
// LDG.128 per warp instead of 1 (MLP 1 -> 4).
__global__ void k_agg128(const float* __restrict__ bias, const float* __restrict__ W3,
                         int n, uint32_t ka, uint32_t kb) {
    const float* H = g_buf0;
    int g = blockIdx.x * blockDim.x + threadIdx.x;
    int v = g >> 5;
    if (v >= n) return;
    int lane = g & 31;
    int s0 = g_starts[v];
    int cnt = g_cnt[v];

    float4 ac0 = make_float4(0.f, 0.f, 0.f, 0.f);
    float4 ac1 = make_float4(0.f, 0.f, 0.f, 0.f);
    float4 ac2 = make_float4(0.f, 0.f, 0.f, 0.f);
    float4 ac3 = make_float4(0.f, 0.f, 0.f, 0.f);

    for (int base = 0; base < cnt; base += 32) {
        int si = 0; float wi = 0.f;
        if (base + lane < cnt) {
            long long p = g_csr[s0 + base + lane];
            si = (int)(unsigned)(p & 0xffffffffll);
            wi = __int_as_float((int)(p >> 32));
        }
        int m = min(32, cnt - base);
        int j = 0;
        for (; j + 4 <= m; j += 4) {
            int sA = __shfl_sync(0xffffffffu, si, j);
            int sB = __shfl_sync(0xffffffffu, si, j + 1);
            int sC = __shfl_sync(0xffffffffu, si, j + 2);
            int sD = __shfl_sync(0xffffffffu, si, j + 3);
            float wA = __shfl_sync(0xffffffffu, wi, j);
            float wB = __shfl_sync(0xffffffffu, wi, j + 1);
            float wC = __shfl_sync(0xffffffffu, wi, j + 2);
            float wD = __shfl_sync(0xffffffffu, wi, j + 3);
            // 4 independent gathers issued back-to-back
            float4 hA = *(const float4*)(H + (size_t)sA * DIM + lane * 4);
            float4 hB = *(const float4*)(H + (size_t)sB * DIM + lane * 4);
            float4 hC = *(const float4*)(H + (size_t)sC * DIM + lane * 4);
            float4 hD = *(const float4*)(H + (size_t)sD * DIM + lane * 4);
            ac0.x += wA * hA.x; ac0.y += wA * hA.y; ac0.z += wA * hA.z; ac0.w += wA * hA.w;
            ac1.x += wB * hB.x; ac1.y += wB * hB.y; ac1.z += wB * hB.z; ac1.w += wB * hB.w;
            ac2.x += wC * hC.x; ac2.y += wC * hC.y; ac2.z += wC * hC.z; ac2.w += wC * hC.w;
            ac3.x += wD * hD.x; ac3.y += wD * hD.y; ac3.z += wD * hD.z; ac3.w += wD * hD.w;
        }
        for (; j < m; j++) {
            int s = __shfl_sync(0xffffffffu, si, j);
            float w = __shfl_sync(0xffffffffu, wi, j);
            float4 hv = *(const float4*)(H + (size_t)s * DIM + lane * 4);
            ac0.x += w * hv.x; ac0.y += w * hv.y;
            ac0.z += w * hv.z; ac0.w += w * hv.w;
        }
    }
    float4 acc = make_float4(ac0.x + ac1.x + ac2.x + ac3.x,
                             ac0.y + ac1.y + ac2.y + ac3.y,
                             ac0.z + ac1.z + ac2.z + ac3.z,
                             ac0.w + ac1.w + ac2.w + ac3.w);
    float dv = g_dis[v];
    float ws = dv * dv;
    float4 hv = *(const float4*)(H + (size_t)v * DIM + lane * 4);
    float4 bv = *(const float4*)(bias + lane * 4);
    acc.x += ws * hv.x + bv.x;
    acc.y += ws * hv.y + bv.y;
    acc.z += ws * hv.z + bv.z;
    acc.w += ws * hv.w + bv.w;

    // leaky_relu + exact-JAX dropout
    {
        uint32_t i0 = (uint32_t)v * DIM + lane * 4;
        float a[4] = {acc.x, acc.y, acc.z, acc.w};
#pragma unroll
        for (int c2 = 0; c2 < 4; c2++) {
            float vv = a[c2];
            vv = (vv >= 0.f) ? vv : 0.01f * vv;
            a[c2] = drop_keep(ka, kb, i0 + c2) ? (vv + vv) : 0.f;
        }
        acc.x = a[0]; acc.y = a[1]; acc.z = a[2]; acc.w = a[3];
    }

    if (W3 == nullptr) {
        *(float4*)(g_buf1 + (size_t)v * DIM + lane * 4) = acc;
    } else {
        // fused layer-3 GEMM: this warp holds the full 128-dim row
        float4 wA = *(const float4*)(W3 + lane * 8);
        float4 wB = *(const float4*)(W3 + lane * 8 + 4);
        float a0 = acc.x * wA.x + acc.y * wA.z + acc.z * wB.x + acc.w * wB.z;
        float a1 = acc.x * wA.y + acc.y * wA.w + acc.z * wB.y + acc.w * wB.w;
#pragma unroll
        for (int off = 16; off > 0; off >>= 1) {
            a0 += __shfl_xor_sync(0xffffffffu, a0, off);
            a1 += __shfl_xor_sync(0xffffffffu, a1, off);
        }
        if (lane == 0) { g_h3[v * 2] = a0; g_h3[v * 2 + 1] = a1; }
    }
}

// ---------------- final aggregation + bias + log_softmax (4 lanes/node) ----------------
__global__ void k_final(const float* __restrict__ b3, float* __restrict__ out, int n) {
    int g = blockIdx.x * blockDim.x + threadIdx.x;
    int v = g >> 2;
    if (v >= n) return;
    int sub = g & 3;
    int s0 = g_starts[v];
    int cnt = g_cnt[v];
    float a0 = 0.f, a1 = 0.f;
    for (int i = sub; i < cnt; i += 4) {
        long long p = g_csr[s0 + i];
        int s = (int)(unsigned)(p & 0xffffffffll);
        float w = __int_as_float((int)(p >> 32));
        a0 += w * g_h3[s * 2];
        a1 += w * g_h3[s * 2 + 1];
    }
#pragma unroll
    for (int off = 1; off < 4; off <<= 1) {
        a0 += __shfl_xor_sync(0xffffffffu, a0, off);
        a1 += __shfl_xor_sync(0xffffffffu, a1, off);
    }
    if (sub == 0) {
        float dv = g_dis[v];
        float wsv = dv * dv;
        a0 += wsv * g_h3[v * 2]     + b3[0];
        a1 += wsv * g_h3[v * 2 + 1] + b3[1];
        float m = fmaxf(a0, a1);
        float lse = m + logf(expf(a0 - m) + expf(a1 - m));
        out[v * 2]     = a0 - lse;
        out[v * 2 + 1] = a1 - lse;
    }
}

// ---------------- launch (round-10 proven schedule; capture safe) ----------------
extern "C" void kernel_launch(void* const* d_in, const int* in_sizes, int n_in,
                              void* d_out, int out_size) {
    const float* x  = (const float*)d_in[0];
    const int*   ei = (const int*)d_in[1];
    const float* W1 = (const float*)d_in[2];
    const float* b1 = (const float*)d_in[3];
    const float* W2 = (const float*)d_in[4];
    const float* b2 = (const float*)d_in[5];
    const float* W3 = (const float*)d_in[6];
    const float* b3 = (const float*)d_in[7];
    float* out = (float*)d_out;

    int n = in_sizes[0] / DIM;      // 50000
    int E = in_sizes[1] / 2;        // 800000

    uint32_t k1a, k1b, k2a, k2b;
    tf2x32(0u, 42u, 0u, 0u, k1a, k1b);
    tf2x32(0u, 42u, 0u, 1u, k2a, k2b);

    static cudaStream_t s_side = nullptr;
    static cudaEvent_t ev_fork = nullptr, ev_join = nullptr;
    if (s_side == nullptr) {
        cudaStreamCreateWithFlags(&s_side, cudaStreamNonBlocking);
        cudaEventCreateWithFlags(&ev_fork, cudaEventDisableTiming);
        cudaEventCreateWithFlags(&ev_join, cudaEventDisableTiming);
    }

    int nb_n = (n + 255) / 256;
    int nb_w = (n * 32 + 255) / 256;
    int nb_g = (n + 127) / 128;
    int nb_f = (n * 4 + 255) / 256;
    int E4 = E >> 2;
    int nb_q = (E4 + (E & 3) + 255) / 256;

    // fork: CSR prep on side stream, concurrent with GEMM1 on main stream
    cudaEventRecord(ev_fork, 0);
    cudaStreamWaitEvent(s_side, ev_fork, 0);
    k_zero_cnt<<<nb_n, 256, 0, s_side>>>(n);
    k_count<<<nb_q, 256, 0, s_side>>>(ei, E);
    k_disres<<<nb_n, 256, 0, s_side>>>(n);
    k_scatter<<<nb_q, 256, 0, s_side>>>(ei, E);
    cudaEventRecord(ev_join, s_side);

    k_gemm128<<<nb_g, 256>>>(x, W1, n);           // main stream, overlaps prep

    cudaStreamWaitEvent(0, ev_join, 0);           // join before agg1

    // layer 1
    k_agg128<<<nb_w, 256>>>(b1, nullptr, n, k1a, k1b);
    // layer 2 (+ fused layer-3 GEMM in agg epilogue)
    k_gemm128<<<nb_g, 256>>>(nullptr, W2, n);
    k_agg128<<<nb_w, 256>>>(b2, W3, n, k2a, k2b);
    // final aggregation + log_softmax
    k_final<<<nb_f, 256>>>(b3, out, n);
}